// round 1
// baseline (speedup 1.0000x reference)
#include <cuda_runtime.h>
#include <cstdint>

// Problem constants
#define B_  2048
#define T_  512
#define I_  58
#define H_  23
#define G_  69          // 3*H
#define GP_ 72          // padded gate dim
#define ROWS_ (B_*T_)   // 1048576

// Scratch for x_proj: [B*T][69]  (uninitialized __device__ global -> no alloc)
__device__ float g_xproj[(size_t)ROWS_ * G_];

// ---------------- f32x2 helpers (packed FFMA2 path, sm_103a) ----------------
__device__ __forceinline__ unsigned long long pk2(float a, float b) {
    unsigned long long r;
    asm("mov.b64 %0, {%1, %2};" : "=l"(r) : "f"(a), "f"(b));
    return r;
}
__device__ __forceinline__ void upk2(unsigned long long v, float& a, float& b) {
    asm("mov.b64 {%0, %1}, %2;" : "=f"(a), "=f"(b) : "l"(v));
}
__device__ __forceinline__ unsigned long long ffma2(unsigned long long a,
                                                    unsigned long long b,
                                                    unsigned long long c) {
    unsigned long long d;
    asm("fma.rn.f32x2 %0, %1, %2, %3;" : "=l"(d) : "l"(a), "l"(b), "l"(c));
    return d;
}
// ---------------- fast transcendentals ----------------
__device__ __forceinline__ float fex2(float x) {
    float y; asm("ex2.approx.f32 %0, %1;" : "=f"(y) : "f"(x)); return y;
}
__device__ __forceinline__ float frcp(float x) {
    float y; asm("rcp.approx.f32 %0, %1;" : "=f"(y) : "f"(x)); return y;
}
__device__ __forceinline__ float fsigmoid(float x) {
    // 1/(1+exp(-x)); large |x| saturates cleanly (ex2 -> inf -> rcp -> 0)
    return frcp(1.0f + fex2(-1.4426950408889634f * x));
}
__device__ __forceinline__ float ftanh(float x) {
    // tanh(x) = 1 - 2/(exp(2x)+1); saturates to +-1 without NaN
    float e = fex2(2.8853900817779268f * x);
    return fmaf(-2.0f, frcp(e + 1.0f), 1.0f);
}

// ============================================================================
// Kernel 1: x_proj[row][g] = dot(task[row][:], W_ih[g][:]) + b_ih[g]
//   block = 384 threads, 128 rows/block; thread = (rg, gg): 4 rows x 6 outputs
//   f32x2: 2 rows per packed lane -> 12 FMA2 per k per thread
// ============================================================================
__global__ __launch_bounds__(384) void gemm_xproj_kernel(
    const float* __restrict__ task,   // [B*T][58]
    const float* __restrict__ Wih,    // [69][58]
    const float* __restrict__ bih)    // [69]
{
    __shared__ __align__(16) float xs[I_ * 128];  // xs[k][r], transposed stage
    __shared__ __align__(16) float ws[I_ * GP_];  // ws[k][g], transposed, padded

    const int tid = threadIdx.x;
    const size_t rowbase = (size_t)blockIdx.x * 128;

    // Stage weights transposed + padded
    for (int i = tid; i < I_ * GP_; i += 384) {
        int k = i / GP_, g = i % GP_;
        ws[i] = (g < G_) ? Wih[g * I_ + k] : 0.0f;
    }
    // Stage x transposed (coalesced global read)
    const float* xg = task + rowbase * I_;
    for (int i = tid; i < 128 * I_; i += 384) {
        int r = i / I_, k = i % I_;
        xs[k * 128 + r] = xg[(size_t)r * I_ + k];
    }
    __syncthreads();

    const int gg = tid % 12;        // 12 * 6 = 72 outputs
    const int rg = tid / 12;        // 32 * 4 = 128 rows
    const int g0 = gg * 6;
    const int r0 = rg * 4;

    unsigned long long acc[2][6];
    #pragma unroll
    for (int gi = 0; gi < 6; gi++) {
        float bv = (g0 + gi < G_) ? bih[g0 + gi] : 0.0f;
        unsigned long long p = pk2(bv, bv);
        acc[0][gi] = p; acc[1][gi] = p;
    }

    #pragma unroll
    for (int k = 0; k < I_; k++) {
        // two row-pairs (rows r0..r0+3) as one LDS.128
        ulonglong2 xv = *reinterpret_cast<const ulonglong2*>(xs + k * 128 + r0);
        unsigned long long x0 = xv.x, x1 = xv.y;
        // six weights (scalar), duplicated into pairs
        const float2* wr = reinterpret_cast<const float2*>(ws + k * GP_ + g0);
        float2 wa = wr[0], wb = wr[1], wc = wr[2];
        unsigned long long wd[6] = {
            pk2(wa.x, wa.x), pk2(wa.y, wa.y),
            pk2(wb.x, wb.x), pk2(wb.y, wb.y),
            pk2(wc.x, wc.x), pk2(wc.y, wc.y)
        };
        #pragma unroll
        for (int gi = 0; gi < 6; gi++) {
            acc[0][gi] = ffma2(x0, wd[gi], acc[0][gi]);
            acc[1][gi] = ffma2(x1, wd[gi], acc[1][gi]);
        }
    }

    // Store 4 rows x 6 outputs (skip padded g)
    #pragma unroll
    for (int p = 0; p < 2; p++) {
        size_t rA = rowbase + r0 + 2 * p;
        #pragma unroll
        for (int gi = 0; gi < 6; gi++) {
            int g = g0 + gi;
            if (g < G_) {
                float lo, hi;
                upk2(acc[p][gi], lo, hi);
                g_xproj[rA * G_ + g]       = lo;
                g_xproj[(rA + 1) * G_ + g] = hi;
            }
        }
    }
}

// ============================================================================
// Kernel 2: GRU scan. One warp per batch row. Lane j (0..22) owns hidden unit j.
//   h exchanged via shared (24 floats, pair-readable). W_hh rows pre-packed
//   into f32x2 pairs over k -> 36 FMA2 per step per lane.
// ============================================================================
__global__ __launch_bounds__(32) void gru_scan_kernel(
    const float* __restrict__ Whh,    // [69][23]
    const float* __restrict__ bhh,    // [69]
    const float* __restrict__ piw,    // [23]
    const float* __restrict__ pib,    // [23]
    float* __restrict__ out_action,   // [B][T][23]
    float* __restrict__ out_hidden)   // [B][23]
{
    __shared__ __align__(16) float hsm[24];

    const int j  = threadIdx.x;
    const int b  = blockIdx.x;
    const int jc = (j < H_) ? j : (H_ - 1);
    const bool act = (j < H_);

    // Pack W_hh rows (r, z, n gates for unit jc) into k-pairs; pad k=23 with 0
    unsigned long long WR[12], WZ[12], WN[12];
    const float* wr = Whh + (size_t)jc * H_;
    const float* wz = Whh + (size_t)(H_ + jc) * H_;
    const float* wn = Whh + (size_t)(2 * H_ + jc) * H_;
    #pragma unroll
    for (int m = 0; m < 12; m++) {
        float a0 = wr[2 * m], a1 = (2 * m + 1 < H_) ? wr[2 * m + 1] : 0.0f;
        WR[m] = pk2(a0, a1);
        float z0 = wz[2 * m], z1 = (2 * m + 1 < H_) ? wz[2 * m + 1] : 0.0f;
        WZ[m] = pk2(z0, z1);
        float n0 = wn[2 * m], n1 = (2 * m + 1 < H_) ? wn[2 * m + 1] : 0.0f;
        WN[m] = pk2(n0, n1);
    }
    const float bhr = bhh[jc], bhz = bhh[H_ + jc], bhn = bhh[2 * H_ + jc];
    const float pw = piw[jc], pb = pib[jc];
    const unsigned long long BR0 = pk2(bhr, 0.0f);
    const unsigned long long BZ0 = pk2(bhz, 0.0f);
    const unsigned long long BN0 = pk2(bhn, 0.0f);

    if (j < 24) hsm[j] = 0.0f;
    __syncwarp();

    float h = 0.0f;
    const float* xp = g_xproj + (size_t)b * T_ * G_;
    float* outp = out_action + (size_t)b * T_ * H_;

    // prefetch t=0
    float cxr = xp[jc], cxz = xp[H_ + jc], cxn = xp[2 * H_ + jc];

    #pragma unroll 2
    for (int t = 0; t < T_; t++) {
        // prefetch next step's x-projection (clamped; redundant last iter)
        const float* nx = xp + (size_t)((t < T_ - 1) ? t + 1 : t) * G_;
        float nxr = nx[jc], nxz = nx[H_ + jc], nxn = nx[2 * H_ + jc];

        // hg = W_hh[gate_rows(j)] . h  (pairs over k via LDS.64)
        unsigned long long aR = BR0, aZ = BZ0, aN = BN0;
        #pragma unroll
        for (int m = 0; m < 12; m++) {
            unsigned long long h2 =
                *reinterpret_cast<const unsigned long long*>(hsm + 2 * m);
            aR = ffma2(WR[m], h2, aR);
            aZ = ffma2(WZ[m], h2, aZ);
            aN = ffma2(WN[m], h2, aN);
        }
        float rlo, rhi, zlo, zhi, nlo, nhi;
        upk2(aR, rlo, rhi); upk2(aZ, zlo, zhi); upk2(aN, nlo, nhi);
        float hr = rlo + rhi, hz = zlo + zhi, hn = nlo + nhi;

        float r = fsigmoid(cxr + hr);
        float z = fsigmoid(cxz + hz);
        float n = ftanh(fmaf(r, hn, cxn));
        float hnew = fmaf(z, h - n, n);   // (1-z)*n + z*h

        __syncwarp();                     // all lanes done reading hsm
        if (act) hsm[j] = hnew;
        __syncwarp();                     // writes visible for next step

        if (act) outp[(size_t)t * H_ + j] = fmaf(pw, hnew, pb);
        h = hnew;
        cxr = nxr; cxz = nxz; cxn = nxn;
    }

    if (act) out_hidden[(size_t)b * H_ + j] = h;
}

// ============================================================================
extern "C" void kernel_launch(void* const* d_in, const int* in_sizes, int n_in,
                              void* d_out, int out_size) {
    const float* task = (const float*)d_in[0];  // (2048,512,58)
    const float* Wih  = (const float*)d_in[1];  // (69,58)
    const float* Whh  = (const float*)d_in[2];  // (69,23)
    const float* bih  = (const float*)d_in[3];  // (69)
    const float* bhh  = (const float*)d_in[4];  // (69)
    const float* piw  = (const float*)d_in[5];  // (23)
    const float* pib  = (const float*)d_in[6];  // (23)

    float* out = (float*)d_out;
    float* action = out;                                  // B*T*H
    float* hidden = out + (size_t)B_ * T_ * H_;           // B*H

    gemm_xproj_kernel<<<ROWS_ / 128, 384>>>(task, Wih, bih);
    gru_scan_kernel<<<B_, 32>>>(Whh, bhh, piw, pib, action, hidden);
}

// round 3
// speedup vs baseline: 1.6841x; 1.6841x over previous
#include <cuda_runtime.h>
#include <cstdint>

typedef unsigned long long ull;

// Problem constants
#define B_  2048
#define T_  512
#define I_  58
#define H_  23
#define G_  69          // 3*H
#define GP_ 72          // padded gate dim (even, float4-friendly)
#define ROWS_ (B_*T_)   // 1048576

// Scratch for x_proj: [B*T][72] padded  (__device__ global -> no runtime alloc)
__device__ float g_xproj[(size_t)ROWS_ * GP_];

// ---------------- f32x2 helpers ----------------
__device__ __forceinline__ ull pk2(float a, float b) {
    ull r;
    asm("mov.b64 %0, {%1, %2};" : "=l"(r) : "f"(a), "f"(b));
    return r;
}
__device__ __forceinline__ void upk2(ull v, float& a, float& b) {
    asm("mov.b64 {%0, %1}, %2;" : "=f"(a), "=f"(b) : "l"(v));
}
__device__ __forceinline__ ull ffma2(ull a, ull b, ull c) {
    ull d;
    asm("fma.rn.f32x2 %0, %1, %2, %3;" : "=l"(d) : "l"(a), "l"(b), "l"(c));
    return d;
}
// ---------------- fast transcendentals ----------------
__device__ __forceinline__ float fex2(float x) {
    float y; asm("ex2.approx.f32 %0, %1;" : "=f"(y) : "f"(x)); return y;
}
__device__ __forceinline__ float frcp(float x) {
    float y; asm("rcp.approx.f32 %0, %1;" : "=f"(y) : "f"(x)); return y;
}
__device__ __forceinline__ float fsigmoid(float x) {
    return frcp(1.0f + fex2(-1.4426950408889634f * x));
}
__device__ __forceinline__ float ftanh(float x) {
    float e = fex2(2.8853900817779268f * x);
    return fmaf(-2.0f, frcp(e + 1.0f), 1.0f);
}

// ============================================================================
// Kernel 1: x_proj[row][g] = dot(task[row][:], W_ih[g][:]) + b_ih[g]
//   192 threads, 128 rows/block. Thread = (rg, gg): 4 rows x 6 g-PAIRS.
//   g-packing: weight pairs load directly as LDS.64 -> FFMA2, no dup movs.
//   Output restaged via smem -> fully coalesced float4 stores (72-pad layout).
// ============================================================================
__global__ __launch_bounds__(192, 4) void gemm_xproj_kernel(
    const float* __restrict__ task,   // [B*T][58]
    const float* __restrict__ Wih,    // [69][58]
    const float* __restrict__ bih)    // [69]
{
    // xs: [128][58] row-major floats (29696B) ; ws: [58][36] g-pairs (16704B)
    // after compute, region reused as os: [128][36] ull output pairs (36864B)
    __shared__ __align__(16) char sraw[128 * I_ * 4 + I_ * 36 * 8];
    float* xs = reinterpret_cast<float*>(sraw);
    ull*   ws = reinterpret_cast<ull*>(sraw + 128 * I_ * 4);
    __shared__ __align__(8) ull bs[36];

    const int tid = threadIdx.x;
    const size_t rowbase = (size_t)blockIdx.x * 128;

    // Stage x tile: coalesced float4 (128*58/4 = 1856 vectors)
    {
        const float4* src = reinterpret_cast<const float4*>(task + rowbase * I_);
        float4* dst = reinterpret_cast<float4*>(xs);
        // 1856 = 9*192 + 128 : 9 full rounds + one guarded round
        #pragma unroll
        for (int it = 0; it < 9; it++) {
            dst[tid + it * 192] = src[tid + it * 192];
        }
        if (tid < 128) dst[tid + 9 * 192] = src[tid + 9 * 192];
    }
    // Stage weights as (k, g-pair) with zero pad beyond g=68
    for (int i = tid; i < I_ * 36; i += 192) {
        int k = i / 36, p = i - 36 * k;
        int g0 = 2 * p;
        float w0 = (g0     < G_) ? Wih[g0 * I_ + k]       : 0.0f;
        float w1 = (g0 + 1 < G_) ? Wih[(g0 + 1) * I_ + k] : 0.0f;
        float2 wp = make_float2(w0, w1);
        ws[i] = *reinterpret_cast<ull*>(&wp);
    }
    if (tid < 36) {
        int g0 = 2 * tid;
        float b0 = (g0     < G_) ? bih[g0]     : 0.0f;
        float b1 = (g0 + 1 < G_) ? bih[g0 + 1] : 0.0f;
        float2 bp = make_float2(b0, b1);
        bs[tid] = *reinterpret_cast<ull*>(&bp);
    }
    __syncthreads();

    const int gg = tid % 6;      // 6 g-pair tiles of 6 pairs each (36 pairs = 72 g)
    const int rg = tid / 6;      // 32 row groups of 4 rows
    const int r0 = rg * 4;
    const ull* wbase = ws + gg * 6;
    const float* xbase = xs + r0 * I_;

    ull acc[4][6];
    #pragma unroll
    for (int p = 0; p < 6; p++) {
        ull bb = bs[gg * 6 + p];
        acc[0][p] = bb; acc[1][p] = bb; acc[2][p] = bb; acc[3][p] = bb;
    }

    #pragma unroll 2
    for (int k = 0; k < I_; k++) {
        ull X[4];
        #pragma unroll
        for (int i = 0; i < 4; i++) {
            float xv = xbase[i * I_ + k];
            X[i] = pk2(xv, xv);
        }
        const ull* wk = wbase + k * 36;
        #pragma unroll
        for (int p = 0; p < 6; p++) {
            ull wp = wk[p];
            acc[0][p] = ffma2(X[0], wp, acc[0][p]);
            acc[1][p] = ffma2(X[1], wp, acc[1][p]);
            acc[2][p] = ffma2(X[2], wp, acc[2][p]);
            acc[3][p] = ffma2(X[3], wp, acc[3][p]);
        }
    }

    __syncthreads();   // xs/ws dead; reuse as output stage
    ull* os = reinterpret_cast<ull*>(sraw);   // [128][36] pairs = [128][72] floats
    #pragma unroll
    for (int i = 0; i < 4; i++) {
        #pragma unroll
        for (int p = 0; p < 6; p++) {
            os[(r0 + i) * 36 + gg * 6 + p] = acc[i][p];
        }
    }
    __syncthreads();
    // Coalesced float4 streamout: 128*72/4 = 2304 vectors, exactly 12 per thread
    {
        const float4* src = reinterpret_cast<const float4*>(sraw);
        float4* dst = reinterpret_cast<float4*>(g_xproj + rowbase * GP_);
        #pragma unroll
        for (int it = 0; it < 12; it++) {
            int idx = tid + it * 192;
            dst[idx] = src[idx];
        }
    }
}

// ============================================================================
// Kernel 2: GRU scan. 4 warps/block (one per batch row), lane j = hidden unit.
//   - h double-buffered in smem (1 syncwarp/step), read as LDS.128 quads
//   - bias folded into pad slot h[23] == 1.0
//   - x_proj consumed via 4-step software-pipelined prefetch (12 LDGs/group)
// ============================================================================
__global__ __launch_bounds__(128, 4) void gru_scan_kernel(
    const float* __restrict__ Whh,    // [69][23]
    const float* __restrict__ bhh,    // [69]
    const float* __restrict__ piw,    // [23]
    const float* __restrict__ pib,    // [23]
    float* __restrict__ out_action,   // [B][T][23]
    float* __restrict__ out_hidden)   // [B][23]
{
    __shared__ __align__(16) float hsm[4][2][32];

    const int j  = threadIdx.x & 31;
    const int w  = threadIdx.x >> 5;
    const int b  = blockIdx.x * 4 + w;
    const int jc = (j < H_) ? j : (H_ - 1);
    const bool act = (j < H_);

    // W_hh rows for unit jc, packed over k into 12 pairs; pad slot (k=23)
    // carries b_hh since h[23] is pinned to 1.0
    ull WR[12], WZ[12], WN[12];
    {
        const float* wr = Whh + (size_t)jc * H_;
        const float* wz = Whh + (size_t)(H_ + jc) * H_;
        const float* wn = Whh + (size_t)(2 * H_ + jc) * H_;
        #pragma unroll
        for (int m = 0; m < 11; m++) {
            WR[m] = pk2(wr[2 * m], wr[2 * m + 1]);
            WZ[m] = pk2(wz[2 * m], wz[2 * m + 1]);
            WN[m] = pk2(wn[2 * m], wn[2 * m + 1]);
        }
        WR[11] = pk2(wr[22], bhh[jc]);
        WZ[11] = pk2(wz[22], bhh[H_ + jc]);
        WN[11] = pk2(wn[22], bhh[2 * H_ + jc]);
    }
    const float pw = piw[jc], pb = pib[jc];

    // init both h buffers: zeros, with pad slot [23] = 1.0 (bias carrier)
    hsm[w][0][j] = (j == 23) ? 1.0f : 0.0f;
    hsm[w][1][j] = (j == 23) ? 1.0f : 0.0f;
    __syncwarp();

    const float* xp = g_xproj + (size_t)b * T_ * GP_;
    float* outp = out_action + (size_t)b * T_ * H_;
    const int o0 = jc, o1 = H_ + jc, o2 = 2 * H_ + jc;

    // prime pipeline with group t=0..3
    float cur[12];
    #pragma unroll
    for (int s = 0; s < 4; s++) {
        const float* xr = xp + s * GP_;
        cur[3 * s + 0] = xr[o0];
        cur[3 * s + 1] = xr[o1];
        cur[3 * s + 2] = xr[o2];
    }

    float h = 0.0f;

    for (int tb = 0; tb < T_; tb += 4) {
        const float* xn_ = xp + (size_t)((tb + 4 < T_) ? tb + 4 : T_ - 4) * GP_;
        #pragma unroll
        for (int s = 0; s < 4; s++) {
            // ---- compute step tb+s with cur[3s..3s+2] ----
            const ulonglong2* hq =
                reinterpret_cast<const ulonglong2*>(hsm[w][s & 1]);
            ull aR = 0ull, aZ = 0ull, aN = 0ull;   // bits of (0.f, 0.f)
            #pragma unroll
            for (int m = 0; m < 6; m++) {
                ulonglong2 q = hq[m];
                aR = ffma2(WR[2 * m], q.x, aR);
                aR = ffma2(WR[2 * m + 1], q.y, aR);
                aZ = ffma2(WZ[2 * m], q.x, aZ);
                aZ = ffma2(WZ[2 * m + 1], q.y, aZ);
                aN = ffma2(WN[2 * m], q.x, aN);
                aN = ffma2(WN[2 * m + 1], q.y, aN);
            }
            float rl, rh, zl, zh, nl, nh;
            upk2(aR, rl, rh); upk2(aZ, zl, zh); upk2(aN, nl, nh);

            float r = fsigmoid(cur[3 * s + 0] + (rl + rh));
            float z = fsigmoid(cur[3 * s + 1] + (zl + zh));
            float n = ftanh(fmaf(r, nl + nh, cur[3 * s + 2]));
            float hnew = fmaf(z, h - n, n);        // (1-z)*n + z*h

            if (act) hsm[w][(s + 1) & 1][j] = hnew;
            __syncwarp();

            if (act) outp[(size_t)(tb + s) * H_ + j] = fmaf(pw, hnew, pb);
            h = hnew;

            // ---- refill this slot for next group (deep prefetch) ----
            cur[3 * s + 0] = xn_[s * GP_ + o0];
            cur[3 * s + 1] = xn_[s * GP_ + o1];
            cur[3 * s + 2] = xn_[s * GP_ + o2];
        }
    }

    if (act) out_hidden[(size_t)b * H_ + j] = h;
}

// ============================================================================
extern "C" void kernel_launch(void* const* d_in, const int* in_sizes, int n_in,
                              void* d_out, int out_size) {
    const float* task = (const float*)d_in[0];  // (2048,512,58)
    const float* Wih  = (const float*)d_in[1];  // (69,58)
    const float* Whh  = (const float*)d_in[2];  // (69,23)
    const float* bih  = (const float*)d_in[3];  // (69)
    const float* bhh  = (const float*)d_in[4];  // (69)
    const float* piw  = (const float*)d_in[5];  // (23)
    const float* pib  = (const float*)d_in[6];  // (23)

    float* out = (float*)d_out;
    float* action = out;                                  // B*T*H
    float* hidden = out + (size_t)B_ * T_ * H_;           // B*H

    gemm_xproj_kernel<<<ROWS_ / 128, 192>>>(task, Wih, bih);
    gru_scan_kernel<<<B_ / 4, 128>>>(Whh, bhh, piw, pib, action, hidden);
}